// round 16
// baseline (speedup 1.0000x reference)
#include <cuda_runtime.h>
#include <cuda_fp16.h>
#include <math.h>
#include <stdint.h>

// ---------------- problem constants ----------------
#define T_TOK   8192
#define D_IN    1024
#define E_NUM   4
#define O_DIM   4096
#define M_PAD   16896          // 132*128
#define MT      132
#define BM      128
#define BN      128
#define NSTAGE  3
#define NT      (O_DIM/BN)     // 32
#define TILE_B  8192           // one 128x32 fp16 tile, contiguous + swizzled
#define STAGE_BYTES (4*TILE_B) // 32768 (BK=64 per stage)
#define SMEM_MAIN  (NSTAGE*STAGE_BYTES)   // 98304
#define SMEM_TOTAL (SMEM_MAIN + 64)
#define W2ROWS  16             // leading grid-y rows of GEMM1 doing W2 convert
#define W1CTAS  512            // leading prep CTAs doing W1 convert
#define CMBROWS 8              // trailing grid-y rows of GEMM2: 256 combine CTAs
#define TOK_PER_CMB 32         // tokens per combine CTA (256*32 = 8192)

// swizzled in-tile byte offset for (row, k), row in [0,128), k in [0,32)
#define TOFF(row, k) ((uint32_t)(row)*64 + (((((k) >> 3) ^ (((row) >> 1) & 3))) << 4) + ((k) & 7) * 2)

// ---------------- device scratch (device-code references only) ----------
__device__ __half g_xs [(size_t)M_PAD * D_IN];
__device__ __half g_w1t[(size_t)E_NUM * O_DIM * D_IN];
__device__ __half g_w2t[(size_t)E_NUM * O_DIM * O_DIM];
__device__ __half g_h  [(size_t)M_PAD * O_DIM];
__device__ __half g_eo [(size_t)M_PAD * O_DIM];
__device__ int    g_tok[M_PAD];
__device__ float  g_gw [M_PAD];
__device__ int    g_te [2*T_TOK];
__device__ float  g_tw [2*T_TOK];
__device__ int    g_slot_of[2*T_TOK];
__device__ int    g_cur[E_NUM];
__device__ int    g_off[E_NUM+1];
__device__ int    g2d[MT];              // per-m-tile GEMM2 completion counters

// ---------------- helpers ----------------
__device__ __forceinline__ uint32_t smem_u32(const void* p) {
    uint32_t a;
    asm("{ .reg .u64 t; cvta.to.shared.u64 t, %1; cvt.u32.u64 %0, t; }" : "=r"(a) : "l"(p));
    return a;
}
__device__ __forceinline__ int ld_acq(const int* p) {
    int v; asm volatile("ld.acquire.gpu.global.b32 %0, [%1];" : "=r"(v) : "l"(p) : "memory");
    return v;
}
#define MBAR_INIT(a, c) \
    asm volatile("mbarrier.init.shared.b64 [%0], %1;" :: "r"(a), "r"(c) : "memory")
#define MBAR_EXPECT_TX(a, b) \
    asm volatile("mbarrier.arrive.expect_tx.shared.b64 _, [%0], %1;" :: "r"(a), "r"(b) : "memory")
#define MBAR_WAIT(addr, parity) do {                                              \
    uint32_t _m = (addr); uint32_t _p = (parity); uint32_t _d;                    \
    asm volatile("{ .reg .pred p; mbarrier.try_wait.parity.acquire.cta.shared::cta.b64 p, [%1], %2; selp.b32 %0,1,0,p; }" \
        : "=r"(_d) : "r"(_m), "r"(_p) : "memory");                                \
    if (!_d) {                                                                    \
        asm volatile("{ .reg .pred P1;\n"                                         \
            "WL_%=: mbarrier.try_wait.parity.acquire.cta.shared::cta.b64 P1, [%0], %1, 0x989680;\n" \
            "@P1 bra.uni WD_%=;\n bra.uni WL_%=;\n WD_%=: }"                      \
            :: "r"(_m), "r"(_p) : "memory");                                      \
    } } while(0)
#define BULK_G2S(dst_u32, src_ptr, bytes, mbar) \
    asm volatile("cp.async.bulk.shared::cta.global.mbarrier::complete_tx::bytes [%0], [%1], %2, [%3];" \
        :: "r"(dst_u32), "l"(src_ptr), "r"(bytes), "r"(mbar) : "memory")
#define LDSM_X4(r0,r1,r2,r3,addr) \
    asm volatile("ldmatrix.sync.aligned.m8n8.x4.shared.b16 {%0,%1,%2,%3}, [%4];" \
        : "=r"(r0), "=r"(r1), "=r"(r2), "=r"(r3) : "r"(addr))

__device__ __forceinline__ void mma16n8k16(float* c, const uint32_t* a, const uint32_t* b) {
    asm volatile(
        "mma.sync.aligned.m16n8k16.row.col.f32.f16.f16.f32 "
        "{%0,%1,%2,%3}, {%4,%5,%6,%7}, {%8,%9}, {%0,%1,%2,%3};"
        : "+f"(c[0]), "+f"(c[1]), "+f"(c[2]), "+f"(c[3])
        : "r"(a[0]), "r"(a[1]), "r"(a[2]), "r"(a[3]), "r"(b[0]), "r"(b[1]));
}
__device__ __forceinline__ uint32_t pack2(float a, float b) {
    __half2 h = __floats2half2_rn(a, b);
    return *(uint32_t*)&h;
}
// tanh-GELU via MUFU (ex2 + rcp)
__device__ __forceinline__ float fast_gelu(float v) {
    float u = v * v;
    float y = v * fmaf(0.0356774081f, u, 0.7978845608f);
    float z; asm("ex2.approx.f32 %0, %1;" : "=f"(z) : "f"(y * 2.885390082f));
    float r; asm("rcp.approx.f32 %0, %1;" : "=f"(r) : "f"(z + 1.0f));
    return v - v * r;
}

// Convert k-blocks [kb0, kb0+nkb) of one (expert e, 128-col strip nc) of
// W [K x O_DIM fp32] into tiled+swizzled fp16 K-major. 128 threads.
__device__ void wconv_chunk(const float* __restrict__ src, __half* __restrict__ dstb,
                            float* t2 /* 32*132 floats */, int e, int nc, int K,
                            int kb0, int nkb)
{
    const int tid = threadIdx.x;
    const int ty = tid >> 5, tx = tid & 31;
    const int n  = tid;
    const int sw = (n >> 1) & 3;
    const int KTW = K / 32;
    const float* sp = src + (size_t)e * K * O_DIM + nc * 128;
    for (int kb = kb0; kb < kb0 + nkb; ++kb) {
#pragma unroll
        for (int j = 0; j < 8; ++j) {
            float4 v = *(const float4*)(sp + (size_t)(kb*32 + ty + 4*j)*O_DIM + tx*4);
            float* d = &t2[(ty + 4*j)*132 + tx*4];
            d[0]=v.x; d[1]=v.y; d[2]=v.z; d[3]=v.w;
        }
        __syncthreads();
        char* dp = (char*)dstb + (((size_t)e*32 + nc)*KTW + kb)*TILE_B + (uint32_t)n*64;
#pragma unroll
        for (int c = 0; c < 4; ++c) {
            uint4 q;
            q.x = pack2(t2[(c*8+0)*132+n], t2[(c*8+1)*132+n]);
            q.y = pack2(t2[(c*8+2)*132+n], t2[(c*8+3)*132+n]);
            q.z = pack2(t2[(c*8+4)*132+n], t2[(c*8+5)*132+n]);
            q.w = pack2(t2[(c*8+6)*132+n], t2[(c*8+7)*132+n]);
            *(uint4*)(dp + ((c ^ sw) << 4)) = q;
        }
        __syncthreads();
    }
}

// ---------------- router ----------------
__global__ void __launch_bounds__(256)
router_kernel(const float* __restrict__ x, const float* __restrict__ Wg,
              const float* __restrict__ bg)
{
    const int warp = threadIdx.x >> 5, lane = threadIdx.x & 31;
    const int t = blockIdx.x * 8 + warp;
    const float* xr = x + (size_t)t * D_IN;
    float a0=0,a1=0,a2=0,a3=0;
    for (int d = lane; d < D_IN; d += 32) {
        float xv = xr[d];
        float4 w = ((const float4*)Wg)[d];
        a0 = fmaf(xv,w.x,a0); a1 = fmaf(xv,w.y,a1);
        a2 = fmaf(xv,w.z,a2); a3 = fmaf(xv,w.w,a3);
    }
#pragma unroll
    for (int o = 16; o; o >>= 1) {
        a0 += __shfl_xor_sync(~0u,a0,o); a1 += __shfl_xor_sync(~0u,a1,o);
        a2 += __shfl_xor_sync(~0u,a2,o); a3 += __shfl_xor_sync(~0u,a3,o);
    }
    if (lane == 0) {
        float l[4] = { a0+bg[0], a1+bg[1], a2+bg[2], a3+bg[3] };
        int i0 = 0;
#pragma unroll
        for (int e = 1; e < 4; ++e) if (l[e] > l[i0]) i0 = e;
        int i1 = -1;
#pragma unroll
        for (int e = 0; e < 4; ++e) { if (e==i0) continue; if (i1<0 || l[e]>l[i1]) i1 = e; }
        float r = expf(l[i1]-l[i0]);
        float w0 = 1.f/(1.f+r), w1 = r*w0;
        g_te[2*t]=i0; g_te[2*t+1]=i1; g_tw[2*t]=w0; g_tw[2*t+1]=w1;
    }
}

// ---------------- offsets: recount g_te locally, zero counters --------------
__global__ void __launch_bounds__(256)
offsets_kernel() {
    __shared__ int cnt[E_NUM];
    const int tid = threadIdx.x;
    if (tid < E_NUM) cnt[tid] = 0;
    __syncthreads();
    int c0=0, c1=0, c2=0, c3=0;
    const int4* te4 = (const int4*)g_te;
    for (int i = tid; i < (2*T_TOK)/4; i += 256) {
        int4 v = te4[i];
        c0 += (v.x==0)+(v.y==0)+(v.z==0)+(v.w==0);
        c1 += (v.x==1)+(v.y==1)+(v.z==1)+(v.w==1);
        c2 += (v.x==2)+(v.y==2)+(v.z==2)+(v.w==2);
        c3 += (v.x==3)+(v.y==3)+(v.z==3)+(v.w==3);
    }
    if (c0) atomicAdd(&cnt[0], c0);
    if (c1) atomicAdd(&cnt[1], c1);
    if (c2) atomicAdd(&cnt[2], c2);
    if (c3) atomicAdd(&cnt[3], c3);
    __syncthreads();
    if (tid == 0) {
        int off = 0;
#pragma unroll
        for (int e = 0; e < E_NUM; ++e) {
            g_off[e] = off; off += (cnt[e]+127)&~127; g_cur[e] = 0;
        }
        g_off[E_NUM] = off;
    }
    if (tid < MT) g2d[tid] = 0;
    for (int s = tid; s < M_PAD; s += 256) g_tok[s] = -1;
}

__global__ void scatter_kernel() {
    const int t = blockIdx.x * blockDim.x + threadIdx.x;
    if (t >= T_TOK) return;
#pragma unroll
    for (int k = 0; k < 2; ++k) {
        int e = g_te[2*t+k];
        int p = atomicAdd(&g_cur[e],1);
        int s = g_off[e] + p;
        g_tok[s] = t; g_gw[s] = g_tw[2*t+k]; g_slot_of[2*t+k] = s;
    }
}

// ---------------- prep: W1-convert chunks FIRST, then gather ----------------
__global__ void __launch_bounds__(128)
prep_kernel(const float* __restrict__ x, const float* __restrict__ W1)
{
    __shared__ float t2[32*132];
    const int bx = blockIdx.x;
    const int tid = threadIdx.x;
    if (bx < W1CTAS) {
        wconv_chunk(W1, g_w1t, t2, bx >> 7, (bx >> 2) & 31, D_IN, (bx & 3)*8, 8);
        return;
    }
    const int s = bx - W1CTAS;
    const int tok = g_tok[s];
    const int k = tid * 8, kin = k & 31;
    char* p = (char*)g_xs + ((size_t)(s >> 7)*(D_IN/32) + (k >> 5))*TILE_B
              + TOFF(s & 127, kin);
    uint4 q;
    if (tok < 0) { q.x=q.y=q.z=q.w=0u; }
    else {
        const float4* xr = (const float4*)(x + (size_t)tok*D_IN + k);
        float4 v0 = xr[0], v1 = xr[1];
        q.x = pack2(v0.x, v0.y); q.y = pack2(v0.z, v0.w);
        q.z = pack2(v1.x, v1.y); q.w = pack2(v1.z, v1.w);
    }
    *(uint4*)p = q;
}

// ---------------- fp16 mma GEMM ------------------------------------------
// FIRST: rows [0, W2ROWS) do W2 convert, rows [W2ROWS, W2ROWS+MT) do GEMM1.
// !FIRST: rows [0, MT) do GEMM2 (+publish g2d), rows [MT, MT+CMBROWS) do
//         spin-gated combine+LN (TOK_PER_CMB tokens per CTA, tail-wave only).
template<bool FIRST>
__global__ void __launch_bounds__(128, 2)
gemm_mma(const float* __restrict__ bias, const float* __restrict__ W2src,
         const float* __restrict__ ln_w, const float* __restrict__ ln_b,
         const float* __restrict__ gate_scale, float* __restrict__ out)
{
    extern __shared__ __align__(128) char smem[];
    const int tid  = threadIdx.x;

    if (FIRST && blockIdx.y < W2ROWS) {      // W2 convert
        const int id = blockIdx.y * NT + blockIdx.x;
        wconv_chunk(W2src, g_w2t, (float*)smem, id >> 7, (id >> 2) & 31,
                    O_DIM, (id & 3)*32, 32);
        return;
    }

    if (!FIRST && blockIdx.y >= MT) {        // ---- combine + LayerNorm ----
        __shared__ float s_red[8];
        __shared__ float s_stat[2];
        float* buf = (float*)smem;           // 4096 floats
        const int cb = ((int)blockIdx.y - MT) * NT + blockIdx.x;   // 0..255
        const int wid = tid >> 5, lane = tid & 31;
        const float gsv = gate_scale[0];
#pragma unroll 1
        for (int j = 0; j < TOK_PER_CMB; ++j) {
            const int t = cb * TOK_PER_CMB + j;
            const int sA = g_slot_of[2*t], sB = g_slot_of[2*t+1];
            if (tid == 0) {
                while (ld_acq(&g2d[sA >> 7]) < NT) {}
                while (ld_acq(&g2d[sB >> 7]) < NT) {}
            }
            __syncthreads();
            const __half2* ea = (const __half2*)(g_eo + (size_t)sA * O_DIM);
            const __half2* eb = (const __half2*)(g_eo + (size_t)sB * O_DIM);
            float sum = 0.f, ssq = 0.f;
            for (int i = tid; i < O_DIM/2; i += 128) {
                float2 a = __half22float2(ea[i]);
                float2 b = __half22float2(eb[i]);
                float2 v = make_float2(gsv*(a.x+b.x), gsv*(a.y+b.y));
                ((float2*)buf)[i] = v;
                sum += v.x + v.y;
                ssq += v.x*v.x + v.y*v.y;
            }
#pragma unroll
            for (int o = 16; o; o >>= 1) {
                sum += __shfl_xor_sync(~0u, sum, o);
                ssq += __shfl_xor_sync(~0u, ssq, o);
            }
            if (lane == 0) { s_red[wid] = sum; s_red[4 + wid] = ssq; }
            __syncthreads();
            if (tid == 0) {
                float v = s_red[0]+s_red[1]+s_red[2]+s_red[3];
                float q = s_red[4]+s_red[5]+s_red[6]+s_red[7];
                float mu = v * (1.f / O_DIM);
                s_stat[0] = mu;
                s_stat[1] = rsqrtf(q * (1.f / O_DIM) - mu*mu + 1e-5f);
            }
            __syncthreads();
            const float mu = s_stat[0], rstd = s_stat[1];
            float4* op = (float4*)(out + (size_t)t * O_DIM);
            const float4* lw = (const float4*)ln_w;
            const float4* lb = (const float4*)ln_b;
            for (int i = tid; i < O_DIM/4; i += 128) {
                float4 v = ((float4*)buf)[i], w = lw[i], b = lb[i];
                op[i] = make_float4((v.x-mu)*rstd*w.x+b.x, (v.y-mu)*rstd*w.y+b.y,
                                    (v.z-mu)*rstd*w.z+b.z, (v.w-mu)*rstd*w.w+b.w);
            }
            __syncthreads();                 // buf/s_red reuse
        }
        return;
    }

    constexpr int K   = FIRST ? D_IN : O_DIM;
    constexpr int KT  = K / 32;
    constexpr int KT2 = K / 64;
    const char* __restrict__ At = (const char*)(FIRST ? g_xs : g_h);
    const char* __restrict__ Bt = (const char*)(FIRST ? g_w1t : g_w2t);

    const int n0 = blockIdx.x * BN;
    const int m0 = ((int)blockIdx.y - (FIRST ? W2ROWS : 0)) * BM;
    if (m0 >= g_off[E_NUM]) {
        // pad tile: still publish completion so no consumer can wait on it
        if (!FIRST && tid == 0) { __threadfence(); atomicAdd(&g2d[m0 >> 7], 1); }
        return;
    }

    const uint32_t sb = smem_u32(smem);
    const uint32_t mb = sb + SMEM_MAIN;
    const int wid  = tid >> 5, lane = tid & 31;
    const int wm   = wid >> 1, wn = wid & 1;

    int e = 0;
#pragma unroll
    for (int i = 1; i < E_NUM; ++i) if (m0 >= g_off[i]) e = i;

    const char* Abase = At + (size_t)(m0 >> 7) * KT * TILE_B;
    const char* Bbase = Bt + ((size_t)e * 32 + (n0 >> 7)) * (size_t)KT * TILE_B;

    if (tid == 0) {
#pragma unroll
        for (int s = 0; s < NSTAGE; ++s) MBAR_INIT(mb + 8*s, 1);
    }
    __syncthreads();
    if (tid == 0) {
#pragma unroll
        for (int p = 0; p < 2; ++p) {
            MBAR_EXPECT_TX(mb + 8*p, STAGE_BYTES);
            BULK_G2S(sb + p*STAGE_BYTES,            Abase + (size_t)p*2*TILE_B, 2*TILE_B, mb + 8*p);
            BULK_G2S(sb + p*STAGE_BYTES + 2*TILE_B, Bbase + (size_t)p*2*TILE_B, 2*TILE_B, mb + 8*p);
        }
    }

    const int hiA = lane >> 4;
    const int hiB = (lane >> 3) & 1;
    uint32_t aoff[4]; int asw[4];
#pragma unroll
    for (int mt = 0; mt < 4; ++mt) {
        int row = wm*64 + mt*16 + (lane & 15);
        aoff[mt] = (uint32_t)row * 64;
        asw[mt]  = (row >> 1) & 3;
    }
    uint32_t boff[4]; int bsw[4];
#pragma unroll
    for (int pr = 0; pr < 4; ++pr) {
        int row = wn*64 + pr*16 + ((lane >> 4) << 3) + (lane & 7);
        boff[pr] = (uint32_t)row * 64;
        bsw[pr]  = (row >> 1) & 3;
    }

    float c[4][8][4];
#pragma unroll
    for (int mt = 0; mt < 4; ++mt)
#pragma unroll
        for (int nt = 0; nt < 8; ++nt)
#pragma unroll
            for (int i = 0; i < 4; ++i) c[mt][nt][i] = 0.f;

    int rs = 0, ws = 2, phase = 0;
    for (int it = 0; it < KT2; ++it) {
        __syncthreads();
        if (tid == 0 && it + 2 < KT2) {
            MBAR_EXPECT_TX(mb + 8*ws, STAGE_BYTES);
            BULK_G2S(sb + ws*STAGE_BYTES,            Abase + (size_t)(it+2)*2*TILE_B, 2*TILE_B, mb + 8*ws);
            BULK_G2S(sb + ws*STAGE_BYTES + 2*TILE_B, Bbase + (size_t)(it+2)*2*TILE_B, 2*TILE_B, mb + 8*ws);
        }
        MBAR_WAIT(mb + 8*rs, phase);

        const uint32_t sa = sb + rs*STAGE_BYTES;
        const uint32_t sB = sa + 2*TILE_B;
#pragma unroll
        for (int ks4 = 0; ks4 < 4; ++ks4) {
            const uint32_t tb  = (uint32_t)(ks4 >> 1) * TILE_B;
            const int      ks2 = (ks4 & 1) * 2;
            uint32_t a[4][4];
#pragma unroll
            for (int mt = 0; mt < 4; ++mt)
                LDSM_X4(a[mt][0], a[mt][1], a[mt][2], a[mt][3],
                        sa + tb + aoff[mt] + (uint32_t)(((ks2 | hiA) ^ asw[mt]) << 4));
            uint32_t b[8][2];
#pragma unroll
            for (int pr = 0; pr < 4; ++pr) {
                uint32_t r0, r1, r2, r3;
                LDSM_X4(r0, r1, r2, r3,
                        sB + tb + boff[pr] + (uint32_t)(((ks2 | hiB) ^ bsw[pr]) << 4));
                b[2*pr][0] = r0; b[2*pr][1] = r1;
                b[2*pr+1][0] = r2; b[2*pr+1][1] = r3;
            }
#pragma unroll
            for (int mt = 0; mt < 4; ++mt)
#pragma unroll
                for (int nt = 0; nt < 8; ++nt)
                    mma16n8k16(c[mt][nt], a[mt], b[nt]);
        }
        if (++rs == NSTAGE) { rs = 0; phase ^= 1; }
        if (++ws == NSTAGE) ws = 0;
    }

    // epilogue
    const int lq = lane >> 2, lr = lane & 3;
#pragma unroll
    for (int mt = 0; mt < 4; ++mt) {
        const int r0 = m0 + wm*64 + mt*16 + lq;
        const int r1 = r0 + 8;
        const float gw0 = FIRST ? 1.f : g_gw[r0];
        const float gw1 = FIRST ? 1.f : g_gw[r1];
#pragma unroll
        for (int nt = 0; nt < 8; ++nt) {
            const int col = n0 + wn*64 + nt*8 + 2*lr;
            const float b0 = bias[e*O_DIM + col];
            const float b1 = bias[e*O_DIM + col + 1];
            float v00 = c[mt][nt][0] + b0, v01 = c[mt][nt][1] + b1;
            float v10 = c[mt][nt][2] + b0, v11 = c[mt][nt][3] + b1;
            if (FIRST) {
                v00 = fast_gelu(v00);
                v01 = fast_gelu(v01);
                v10 = fast_gelu(v10);
                v11 = fast_gelu(v11);
                const size_t kb = col >> 5;
                const int kin = col & 31;
                char* p0 = (char*)g_h + ((size_t)(r0 >> 7)*(O_DIM/32) + kb)*TILE_B + TOFF(r0 & 127, kin);
                char* p1 = (char*)g_h + ((size_t)(r1 >> 7)*(O_DIM/32) + kb)*TILE_B + TOFF(r1 & 127, kin);
                *(__half2*)p0 = __floats2half2_rn(v00, v01);
                *(__half2*)p1 = __floats2half2_rn(v10, v11);
            } else {
                *(__half2*)(g_eo + (size_t)r0*O_DIM + col) = __floats2half2_rn(v00*gw0, v01*gw0);
                *(__half2*)(g_eo + (size_t)r1*O_DIM + col) = __floats2half2_rn(v10*gw1, v11*gw1);
            }
        }
    }
    if (!FIRST) {                            // publish tile completion
        __syncthreads();
        if (tid == 0) { __threadfence(); atomicAdd(&g2d[m0 >> 7], 1); }
    }
}

// ---------------- launch ----------------
extern "C" void kernel_launch(void* const* d_in, const int* in_sizes, int n_in,
                              void* d_out, int out_size)
{
    (void)in_sizes; (void)n_in; (void)out_size;
    const float* x  = (const float*)d_in[0];
    const float* Wg = (const float*)d_in[1];
    const float* bg = (const float*)d_in[2];
    const float* W1 = (const float*)d_in[3];
    const float* b1 = (const float*)d_in[4];
    const float* W2 = (const float*)d_in[5];
    const float* b2 = (const float*)d_in[6];
    const float* lw = (const float*)d_in[7];
    const float* lb = (const float*)d_in[8];
    const float* gs = (const float*)d_in[9];
    float* out = (float*)d_out;

    cudaFuncSetAttribute(gemm_mma<true>,  cudaFuncAttributeMaxDynamicSharedMemorySize, SMEM_TOTAL);
    cudaFuncSetAttribute(gemm_mma<false>, cudaFuncAttributeMaxDynamicSharedMemorySize, SMEM_TOTAL);

    router_kernel<<<T_TOK/8, 256>>>(x, Wg, bg);
    offsets_kernel<<<1, 256>>>();
    scatter_kernel<<<T_TOK/256, 256>>>();
    prep_kernel<<<W1CTAS + M_PAD, 128>>>(x, W1);
    gemm_mma<true ><<<dim3(NT, W2ROWS + MT), 128, SMEM_TOTAL>>>(b1, W2, nullptr, nullptr, nullptr, nullptr);
    gemm_mma<false><<<dim3(NT, MT + CMBROWS), 128, SMEM_TOTAL>>>(b2, nullptr, lw, lb, gs, out);
}

// round 17
// speedup vs baseline: 1.1161x; 1.1161x over previous
#include <cuda_runtime.h>
#include <cuda_fp16.h>
#include <math.h>
#include <stdint.h>

// ---------------- problem constants ----------------
#define T_TOK   8192
#define D_IN    1024
#define E_NUM   4
#define O_DIM   4096
#define M_PAD   16896          // 132*128
#define MT      132
#define BM      128
#define BN      128
#define NSTAGE  3
#define NT      (O_DIM/BN)     // 32
#define TILE_B  8192           // one 128x32 fp16 tile, contiguous + swizzled
#define STAGE_BYTES (4*TILE_B) // 32768 (BK=64 per stage)
#define SMEM_MAIN  (NSTAGE*STAGE_BYTES)   // 98304
#define SMEM_TOTAL (SMEM_MAIN + 64)
#define W2ROWS  16             // converter rows interleaved into GEMM1 grid (y%9==4)
#define W1CTAS  512            // leading prep CTAs doing W1 convert

// swizzled in-tile byte offset for (row, k), row in [0,128), k in [0,32)
#define TOFF(row, k) ((uint32_t)(row)*64 + (((((k) >> 3) ^ (((row) >> 1) & 3))) << 4) + ((k) & 7) * 2)

// ---------------- device scratch (device-code references only) ----------
__device__ __half g_xs [(size_t)M_PAD * D_IN];
__device__ __half g_w1t[(size_t)E_NUM * O_DIM * D_IN];
__device__ __half g_w2t[(size_t)E_NUM * O_DIM * O_DIM];
__device__ __half g_h  [(size_t)M_PAD * O_DIM];
__device__ __half g_eo [(size_t)M_PAD * O_DIM];
__device__ int    g_tok[M_PAD];
__device__ float  g_gw [M_PAD];
__device__ int    g_te [2*T_TOK];
__device__ float  g_tw [2*T_TOK];
__device__ int    g_slot_of[2*T_TOK];
__device__ int    g_cur[E_NUM];
__device__ int    g_off[E_NUM+1];

// ---------------- helpers ----------------
__device__ __forceinline__ uint32_t smem_u32(const void* p) {
    uint32_t a;
    asm("{ .reg .u64 t; cvta.to.shared.u64 t, %1; cvt.u32.u64 %0, t; }" : "=r"(a) : "l"(p));
    return a;
}
#define MBAR_INIT(a, c) \
    asm volatile("mbarrier.init.shared.b64 [%0], %1;" :: "r"(a), "r"(c) : "memory")
#define MBAR_EXPECT_TX(a, b) \
    asm volatile("mbarrier.arrive.expect_tx.shared.b64 _, [%0], %1;" :: "r"(a), "r"(b) : "memory")
#define MBAR_WAIT(addr, parity) do {                                              \
    uint32_t _m = (addr); uint32_t _p = (parity); uint32_t _d;                    \
    asm volatile("{ .reg .pred p; mbarrier.try_wait.parity.acquire.cta.shared::cta.b64 p, [%1], %2; selp.b32 %0,1,0,p; }" \
        : "=r"(_d) : "r"(_m), "r"(_p) : "memory");                                \
    if (!_d) {                                                                    \
        asm volatile("{ .reg .pred P1;\n"                                         \
            "WL_%=: mbarrier.try_wait.parity.acquire.cta.shared::cta.b64 P1, [%0], %1, 0x989680;\n" \
            "@P1 bra.uni WD_%=;\n bra.uni WL_%=;\n WD_%=: }"                      \
            :: "r"(_m), "r"(_p) : "memory");                                      \
    } } while(0)
#define BULK_G2S(dst_u32, src_ptr, bytes, mbar) \
    asm volatile("cp.async.bulk.shared::cta.global.mbarrier::complete_tx::bytes [%0], [%1], %2, [%3];" \
        :: "r"(dst_u32), "l"(src_ptr), "r"(bytes), "r"(mbar) : "memory")
#define LDSM_X4(r0,r1,r2,r3,addr) \
    asm volatile("ldmatrix.sync.aligned.m8n8.x4.shared.b16 {%0,%1,%2,%3}, [%4];" \
        : "=r"(r0), "=r"(r1), "=r"(r2), "=r"(r3) : "r"(addr))

__device__ __forceinline__ void mma16n8k16(float* c, const uint32_t* a, const uint32_t* b) {
    asm volatile(
        "mma.sync.aligned.m16n8k16.row.col.f32.f16.f16.f32 "
        "{%0,%1,%2,%3}, {%4,%5,%6,%7}, {%8,%9}, {%0,%1,%2,%3};"
        : "+f"(c[0]), "+f"(c[1]), "+f"(c[2]), "+f"(c[3])
        : "r"(a[0]), "r"(a[1]), "r"(a[2]), "r"(a[3]), "r"(b[0]), "r"(b[1]));
}
__device__ __forceinline__ uint32_t pack2(float a, float b) {
    __half2 h = __floats2half2_rn(a, b);
    return *(uint32_t*)&h;
}
// tanh-GELU via MUFU (ex2 + rcp)
__device__ __forceinline__ float fast_gelu(float v) {
    float u = v * v;
    float y = v * fmaf(0.0356774081f, u, 0.7978845608f);
    float z; asm("ex2.approx.f32 %0, %1;" : "=f"(z) : "f"(y * 2.885390082f));
    float r; asm("rcp.approx.f32 %0, %1;" : "=f"(r) : "f"(z + 1.0f));
    return v - v * r;
}

// Convert k-blocks [kb0, kb0+nkb) of one (expert e, 128-col strip nc) of
// W [K x O_DIM fp32] into tiled+swizzled fp16 K-major. 128 threads.
__device__ void wconv_chunk(const float* __restrict__ src, __half* __restrict__ dstb,
                            float* t2 /* 32*132 floats */, int e, int nc, int K,
                            int kb0, int nkb)
{
    const int tid = threadIdx.x;
    const int ty = tid >> 5, tx = tid & 31;
    const int n  = tid;
    const int sw = (n >> 1) & 3;
    const int KTW = K / 32;
    const float* sp = src + (size_t)e * K * O_DIM + nc * 128;
    for (int kb = kb0; kb < kb0 + nkb; ++kb) {
#pragma unroll
        for (int j = 0; j < 8; ++j) {
            float4 v = *(const float4*)(sp + (size_t)(kb*32 + ty + 4*j)*O_DIM + tx*4);
            float* d = &t2[(ty + 4*j)*132 + tx*4];
            d[0]=v.x; d[1]=v.y; d[2]=v.z; d[3]=v.w;
        }
        __syncthreads();
        char* dp = (char*)dstb + (((size_t)e*32 + nc)*KTW + kb)*TILE_B + (uint32_t)n*64;
#pragma unroll
        for (int c = 0; c < 4; ++c) {
            uint4 q;
            q.x = pack2(t2[(c*8+0)*132+n], t2[(c*8+1)*132+n]);
            q.y = pack2(t2[(c*8+2)*132+n], t2[(c*8+3)*132+n]);
            q.z = pack2(t2[(c*8+4)*132+n], t2[(c*8+5)*132+n]);
            q.w = pack2(t2[(c*8+6)*132+n], t2[(c*8+7)*132+n]);
            *(uint4*)(dp + ((c ^ sw) << 4)) = q;
        }
        __syncthreads();
    }
}

// ---------------- router ----------------
__global__ void __launch_bounds__(256)
router_kernel(const float* __restrict__ x, const float* __restrict__ Wg,
              const float* __restrict__ bg)
{
    const int warp = threadIdx.x >> 5, lane = threadIdx.x & 31;
    const int t = blockIdx.x * 8 + warp;
    const float* xr = x + (size_t)t * D_IN;
    float a0=0,a1=0,a2=0,a3=0;
    for (int d = lane; d < D_IN; d += 32) {
        float xv = xr[d];
        float4 w = ((const float4*)Wg)[d];
        a0 = fmaf(xv,w.x,a0); a1 = fmaf(xv,w.y,a1);
        a2 = fmaf(xv,w.z,a2); a3 = fmaf(xv,w.w,a3);
    }
#pragma unroll
    for (int o = 16; o; o >>= 1) {
        a0 += __shfl_xor_sync(~0u,a0,o); a1 += __shfl_xor_sync(~0u,a1,o);
        a2 += __shfl_xor_sync(~0u,a2,o); a3 += __shfl_xor_sync(~0u,a3,o);
    }
    if (lane == 0) {
        float l[4] = { a0+bg[0], a1+bg[1], a2+bg[2], a3+bg[3] };
        int i0 = 0;
#pragma unroll
        for (int e = 1; e < 4; ++e) if (l[e] > l[i0]) i0 = e;
        int i1 = -1;
#pragma unroll
        for (int e = 0; e < 4; ++e) { if (e==i0) continue; if (i1<0 || l[e]>l[i1]) i1 = e; }
        float r = expf(l[i1]-l[i0]);
        float w0 = 1.f/(1.f+r), w1 = r*w0;
        g_te[2*t]=i0; g_te[2*t+1]=i1; g_tw[2*t]=w0; g_tw[2*t+1]=w1;
    }
}

// ---------------- offsets: recount g_te locally, 128-aligned segments -------
__global__ void __launch_bounds__(256)
offsets_kernel() {
    __shared__ int cnt[E_NUM];
    const int tid = threadIdx.x;
    if (tid < E_NUM) cnt[tid] = 0;
    __syncthreads();
    int c0=0, c1=0, c2=0, c3=0;
    const int4* te4 = (const int4*)g_te;
    for (int i = tid; i < (2*T_TOK)/4; i += 256) {
        int4 v = te4[i];
        c0 += (v.x==0)+(v.y==0)+(v.z==0)+(v.w==0);
        c1 += (v.x==1)+(v.y==1)+(v.z==1)+(v.w==1);
        c2 += (v.x==2)+(v.y==2)+(v.z==2)+(v.w==2);
        c3 += (v.x==3)+(v.y==3)+(v.z==3)+(v.w==3);
    }
    if (c0) atomicAdd(&cnt[0], c0);
    if (c1) atomicAdd(&cnt[1], c1);
    if (c2) atomicAdd(&cnt[2], c2);
    if (c3) atomicAdd(&cnt[3], c3);
    __syncthreads();
    if (tid == 0) {
        int off = 0;
#pragma unroll
        for (int e = 0; e < E_NUM; ++e) {
            g_off[e] = off; off += (cnt[e]+127)&~127; g_cur[e] = 0;
        }
        g_off[E_NUM] = off;
    }
    for (int s = tid; s < M_PAD; s += 256) g_tok[s] = -1;
}

__global__ void scatter_kernel() {
    const int t = blockIdx.x * blockDim.x + threadIdx.x;
    if (t >= T_TOK) return;
#pragma unroll
    for (int k = 0; k < 2; ++k) {
        int e = g_te[2*t+k];
        int p = atomicAdd(&g_cur[e],1);
        int s = g_off[e] + p;
        g_tok[s] = t; g_gw[s] = g_tw[2*t+k]; g_slot_of[2*t+k] = s;
    }
}

// ---------------- prep: W1-convert chunks FIRST, then gather ----------------
__global__ void __launch_bounds__(128)
prep_kernel(const float* __restrict__ x, const float* __restrict__ W1)
{
    __shared__ float t2[32*132];
    const int bx = blockIdx.x;
    const int tid = threadIdx.x;
    if (bx < W1CTAS) {
        wconv_chunk(W1, g_w1t, t2, bx >> 7, (bx >> 2) & 31, D_IN, (bx & 3)*8, 8);
        return;
    }
    const int s = bx - W1CTAS;
    const int tok = g_tok[s];
    const int k = tid * 8, kin = k & 31;
    char* p = (char*)g_xs + ((size_t)(s >> 7)*(D_IN/32) + (k >> 5))*TILE_B
              + TOFF(s & 127, kin);
    uint4 q;
    if (tok < 0) { q.x=q.y=q.z=q.w=0u; }
    else {
        const float4* xr = (const float4*)(x + (size_t)tok*D_IN + k);
        float4 v0 = xr[0], v1 = xr[1];
        q.x = pack2(v0.x, v0.y); q.y = pack2(v0.z, v0.w);
        q.z = pack2(v1.x, v1.y); q.w = pack2(v1.z, v1.w);
    }
    *(uint4*)p = q;
}

// ---------------- fp16 mma GEMM (+ INTERLEAVED W2 convert on FIRST) ---------
// FIRST: grid-y rows with (y % 9 == 4) are W2-converter rows (16 of 148),
//        spread through the dispatch so their DRAM work overlaps GEMM1.
template<bool FIRST>
__global__ void __launch_bounds__(128, 2)
gemm_mma(const float* __restrict__ bias, const float* __restrict__ W2src)
{
    extern __shared__ __align__(128) char smem[];
    const int tid  = threadIdx.x;

    int m0;
    if (FIRST) {
        const int y = blockIdx.y;
        if (y % 9 == 4) {                   // interleaved W2 converter row
            const int id = (y / 9) * NT + blockIdx.x;   // 0..511
            wconv_chunk(W2src, g_w2t, (float*)smem, id >> 7, (id >> 2) & 31,
                        O_DIM, (id & 3)*32, 32);
            return;
        }
        m0 = (y - (y + 5) / 9) * BM;        // skip converter rows
    } else {
        m0 = blockIdx.y * BM;
    }

    constexpr int K   = FIRST ? D_IN : O_DIM;
    constexpr int KT  = K / 32;
    constexpr int KT2 = K / 64;
    const char* __restrict__ At = (const char*)(FIRST ? g_xs : g_h);
    const char* __restrict__ Bt = (const char*)(FIRST ? g_w1t : g_w2t);

    const int n0 = blockIdx.x * BN;
    if (m0 >= g_off[E_NUM]) return;

    const uint32_t sb = smem_u32(smem);
    const uint32_t mb = sb + SMEM_MAIN;
    const int wid  = tid >> 5, lane = tid & 31;
    const int wm   = wid >> 1, wn = wid & 1;

    int e = 0;
#pragma unroll
    for (int i = 1; i < E_NUM; ++i) if (m0 >= g_off[i]) e = i;

    const char* Abase = At + (size_t)(m0 >> 7) * KT * TILE_B;
    const char* Bbase = Bt + ((size_t)e * 32 + (n0 >> 7)) * (size_t)KT * TILE_B;

    if (tid == 0) {
#pragma unroll
        for (int s = 0; s < NSTAGE; ++s) MBAR_INIT(mb + 8*s, 1);
    }
    __syncthreads();
    if (tid == 0) {
#pragma unroll
        for (int p = 0; p < 2; ++p) {
            MBAR_EXPECT_TX(mb + 8*p, STAGE_BYTES);
            BULK_G2S(sb + p*STAGE_BYTES,            Abase + (size_t)p*2*TILE_B, 2*TILE_B, mb + 8*p);
            BULK_G2S(sb + p*STAGE_BYTES + 2*TILE_B, Bbase + (size_t)p*2*TILE_B, 2*TILE_B, mb + 8*p);
        }
    }

    const int hiA = lane >> 4;
    const int hiB = (lane >> 3) & 1;
    uint32_t aoff[4]; int asw[4];
#pragma unroll
    for (int mt = 0; mt < 4; ++mt) {
        int row = wm*64 + mt*16 + (lane & 15);
        aoff[mt] = (uint32_t)row * 64;
        asw[mt]  = (row >> 1) & 3;
    }
    uint32_t boff[4]; int bsw[4];
#pragma unroll
    for (int pr = 0; pr < 4; ++pr) {
        int row = wn*64 + pr*16 + ((lane >> 4) << 3) + (lane & 7);
        boff[pr] = (uint32_t)row * 64;
        bsw[pr]  = (row >> 1) & 3;
    }

    float c[4][8][4];
#pragma unroll
    for (int mt = 0; mt < 4; ++mt)
#pragma unroll
        for (int nt = 0; nt < 8; ++nt)
#pragma unroll
            for (int i = 0; i < 4; ++i) c[mt][nt][i] = 0.f;

    int rs = 0, ws = 2, phase = 0;
    for (int it = 0; it < KT2; ++it) {
        __syncthreads();
        if (tid == 0 && it + 2 < KT2) {
            MBAR_EXPECT_TX(mb + 8*ws, STAGE_BYTES);
            BULK_G2S(sb + ws*STAGE_BYTES,            Abase + (size_t)(it+2)*2*TILE_B, 2*TILE_B, mb + 8*ws);
            BULK_G2S(sb + ws*STAGE_BYTES + 2*TILE_B, Bbase + (size_t)(it+2)*2*TILE_B, 2*TILE_B, mb + 8*ws);
        }
        MBAR_WAIT(mb + 8*rs, phase);

        const uint32_t sa = sb + rs*STAGE_BYTES;
        const uint32_t sB = sa + 2*TILE_B;
#pragma unroll
        for (int ks4 = 0; ks4 < 4; ++ks4) {
            const uint32_t tb  = (uint32_t)(ks4 >> 1) * TILE_B;
            const int      ks2 = (ks4 & 1) * 2;
            uint32_t a[4][4];
#pragma unroll
            for (int mt = 0; mt < 4; ++mt)
                LDSM_X4(a[mt][0], a[mt][1], a[mt][2], a[mt][3],
                        sa + tb + aoff[mt] + (uint32_t)(((ks2 | hiA) ^ asw[mt]) << 4));
            uint32_t b[8][2];
#pragma unroll
            for (int pr = 0; pr < 4; ++pr) {
                uint32_t r0, r1, r2, r3;
                LDSM_X4(r0, r1, r2, r3,
                        sB + tb + boff[pr] + (uint32_t)(((ks2 | hiB) ^ bsw[pr]) << 4));
                b[2*pr][0] = r0; b[2*pr][1] = r1;
                b[2*pr+1][0] = r2; b[2*pr+1][1] = r3;
            }
#pragma unroll
            for (int mt = 0; mt < 4; ++mt)
#pragma unroll
                for (int nt = 0; nt < 8; ++nt)
                    mma16n8k16(c[mt][nt], a[mt], b[nt]);
        }
        if (++rs == NSTAGE) { rs = 0; phase ^= 1; }
        if (++ws == NSTAGE) ws = 0;
    }

    // epilogue
    const int lq = lane >> 2, lr = lane & 3;
#pragma unroll
    for (int mt = 0; mt < 4; ++mt) {
        const int r0 = m0 + wm*64 + mt*16 + lq;
        const int r1 = r0 + 8;
        const float gw0 = FIRST ? 1.f : g_gw[r0];
        const float gw1 = FIRST ? 1.f : g_gw[r1];
#pragma unroll
        for (int nt = 0; nt < 8; ++nt) {
            const int col = n0 + wn*64 + nt*8 + 2*lr;
            const float b0 = bias[e*O_DIM + col];
            const float b1 = bias[e*O_DIM + col + 1];
            float v00 = c[mt][nt][0] + b0, v01 = c[mt][nt][1] + b1;
            float v10 = c[mt][nt][2] + b0, v11 = c[mt][nt][3] + b1;
            if (FIRST) {
                v00 = fast_gelu(v00);
                v01 = fast_gelu(v01);
                v10 = fast_gelu(v10);
                v11 = fast_gelu(v11);
                const size_t kb = col >> 5;
                const int kin = col & 31;
                char* p0 = (char*)g_h + ((size_t)(r0 >> 7)*(O_DIM/32) + kb)*TILE_B + TOFF(r0 & 127, kin);
                char* p1 = (char*)g_h + ((size_t)(r1 >> 7)*(O_DIM/32) + kb)*TILE_B + TOFF(r1 & 127, kin);
                *(__half2*)p0 = __floats2half2_rn(v00, v01);
                *(__half2*)p1 = __floats2half2_rn(v10, v11);
            } else {
                *(__half2*)(g_eo + (size_t)r0*O_DIM + col) = __floats2half2_rn(v00*gw0, v01*gw0);
                *(__half2*)(g_eo + (size_t)r1*O_DIM + col) = __floats2half2_rn(v10*gw1, v11*gw1);
            }
        }
    }
}

// ---------------- combine (fp16, uint4 loads) + LayerNorm, single-pass ------
__global__ void __launch_bounds__(256)
combine_ln_kernel(const float* __restrict__ ln_w, const float* __restrict__ ln_b,
                  const float* __restrict__ gate_scale, float* __restrict__ out)
{
    __shared__ __align__(16) float buf[O_DIM];
    __shared__ float s_red[64];
    __shared__ float s_mean, s_rstd;

    const int t = blockIdx.x, tid = threadIdx.x;
    const int sA = g_slot_of[2*t], sB = g_slot_of[2*t+1];
    const uint4* ea = (const uint4*)(g_eo + (size_t)sA * O_DIM);   // 8 halves each
    const uint4* eb = (const uint4*)(g_eo + (size_t)sB * O_DIM);
    const float gs = gate_scale[0];

    float sum = 0.f, ssq = 0.f;
#pragma unroll
    for (int r = 0; r < 2; ++r) {                     // 512 uint4 / 256 threads
        const int i = tid + r*256;
        uint4 qa = ea[i], qb = eb[i];
        const __half2* ha = (const __half2*)&qa;
        const __half2* hb = (const __half2*)&qb;
        float2* bo = (float2*)buf + i*4;
#pragma unroll
        for (int j = 0; j < 4; ++j) {
            float2 a = __half22float2(ha[j]);
            float2 b = __half22float2(hb[j]);
            float2 v = make_float2(gs*(a.x+b.x), gs*(a.y+b.y));
            bo[j] = v;
            sum += v.x + v.y;
            ssq += v.x*v.x + v.y*v.y;
        }
    }
#pragma unroll
    for (int o = 16; o; o >>= 1) {
        sum += __shfl_xor_sync(~0u, sum, o);
        ssq += __shfl_xor_sync(~0u, ssq, o);
    }
    if ((tid & 31) == 0) { s_red[tid >> 5] = sum; s_red[32 + (tid >> 5)] = ssq; }
    __syncthreads();
    if (tid < 32) {
        float v = (tid < 8) ? s_red[tid] : 0.f;
        float q = (tid < 8) ? s_red[32 + tid] : 0.f;
#pragma unroll
        for (int o = 4; o; o >>= 1) {
            v += __shfl_xor_sync(~0u, v, o);
            q += __shfl_xor_sync(~0u, q, o);
        }
        if (tid == 0) {
            float mu = v * (1.f / O_DIM);
            s_mean = mu;
            s_rstd = rsqrtf(q * (1.f / O_DIM) - mu*mu + 1e-5f);
        }
    }
    __syncthreads();
    const float mu = s_mean, rstd = s_rstd;

    float4* op = (float4*)(out + (size_t)t * O_DIM);
    const float4* lw = (const float4*)ln_w;
    const float4* lb = (const float4*)ln_b;
    for (int i = tid; i < O_DIM/4; i += 256) {
        float4 v = ((float4*)buf)[i], w = lw[i], b = lb[i];
        op[i] = make_float4((v.x-mu)*rstd*w.x+b.x, (v.y-mu)*rstd*w.y+b.y,
                            (v.z-mu)*rstd*w.z+b.z, (v.w-mu)*rstd*w.w+b.w);
    }
}

// ---------------- launch ----------------
extern "C" void kernel_launch(void* const* d_in, const int* in_sizes, int n_in,
                              void* d_out, int out_size)
{
    (void)in_sizes; (void)n_in; (void)out_size;
    const float* x  = (const float*)d_in[0];
    const float* Wg = (const float*)d_in[1];
    const float* bg = (const float*)d_in[2];
    const float* W1 = (const float*)d_in[3];
    const float* b1 = (const float*)d_in[4];
    const float* W2 = (const float*)d_in[5];
    const float* b2 = (const float*)d_in[6];
    const float* lw = (const float*)d_in[7];
    const float* lb = (const float*)d_in[8];
    const float* gs = (const float*)d_in[9];
    float* out = (float*)d_out;

    cudaFuncSetAttribute(gemm_mma<true>,  cudaFuncAttributeMaxDynamicSharedMemorySize, SMEM_TOTAL);
    cudaFuncSetAttribute(gemm_mma<false>, cudaFuncAttributeMaxDynamicSharedMemorySize, SMEM_TOTAL);

    router_kernel<<<T_TOK/8, 256>>>(x, Wg, bg);
    offsets_kernel<<<1, 256>>>();
    scatter_kernel<<<T_TOK/256, 256>>>();
    prep_kernel<<<W1CTAS + M_PAD, 128>>>(x, W1);
    gemm_mma<true ><<<dim3(NT, W2ROWS + MT), 128, SMEM_TOTAL>>>(b1, W2);  // W2conv interleaved
    gemm_mma<false><<<dim3(NT, MT), 128, SMEM_TOTAL>>>(b2, nullptr);
    combine_ln_kernel<<<T_TOK, 256>>>(lw, lb, gs, out);
}